// round 5
// baseline (speedup 1.0000x reference)
#include <cuda_runtime.h>
#include <cstdint>

#define MAXN 100000
#define MAXE 1000000
#define DIN 128
#define DH  64
#define SCAN_CHUNK 512
#define MAXB 256   // >= ceil(MAXN/SCAN_CHUNK) = 196

// ---- scratch (no allocations allowed; referenced only from device code) ----
__device__ int   g_deg[MAXN];
__device__ int   g_rowptr[MAXN + 1];
__device__ int   g_cursor[MAXN];
__device__ int   g_col[MAXE];
__device__ float g_dinv[MAXN];
__device__ int   g_bsum[MAXB];
__device__ int   g_boff[MAXB];
__device__ __align__(16) float g_h[(size_t)MAXN * 64];  // dinv-scaled GEMM output
__device__ __align__(16) float g_a[(size_t)MAXN * 64];  // layer-1 activations
__device__ int   g_is64;                                 // edge dtype flag

// ---------------- dtype detection: int64 vs int32 edge_index ----------------
__global__ void k_detect(const void* ei, int n, int e) {
    const long long* p = (const long long*)ei;
    int lane = threadIdx.x;
    int bad = 0;
    #pragma unroll
    for (int j = 0; j < 2; j++) {
        int i = lane * 2 + j;
        if (i < e) {
            long long v = p[i];
            if (v < 0 || v >= n) bad = 1;
        }
    }
    unsigned m = __ballot_sync(0xffffffffu, bad);
    if (lane == 0) g_is64 = (m == 0u);
}

// ---------------- init: zero deg ----------------
__global__ void k_init(int n) {
    int i = blockIdx.x * blockDim.x + threadIdx.x;
    if (i < n) g_deg[i] = 0;
}

// ---------------- degree count over dst ----------------
__global__ void k_count(const void* __restrict__ ei, int n, int e) {
    int i = blockIdx.x * blockDim.x + threadIdx.x;
    if (i >= e) return;
    int v;
    if (g_is64) v = (int)((const long long*)ei + e)[i];
    else        v = ((const int*)ei + e)[i];
    if ((unsigned)v < (unsigned)n) atomicAdd(&g_deg[v], 1);
}

// ---------------- phase A: per-block sums of deg ----------------
__global__ void k_part(int n) {
    __shared__ int wsum[8];
    int b = blockIdx.x, t = threadIdx.x;
    int i0 = b * SCAN_CHUNK + t * 2;
    int d0 = (i0     < n) ? g_deg[i0]     : 0;
    int d1 = (i0 + 1 < n) ? g_deg[i0 + 1] : 0;
    int s = d0 + d1;
    #pragma unroll
    for (int off = 16; off > 0; off >>= 1)
        s += __shfl_down_sync(0xffffffffu, s, off);
    int lane = t & 31, w = t >> 5;
    if (lane == 0) wsum[w] = s;
    __syncthreads();
    if (t == 0) {
        int tot = 0;
        #pragma unroll
        for (int k = 0; k < 8; k++) tot += wsum[k];
        g_bsum[b] = tot;
    }
}

// ---------------- phase B: scan block sums (single block) ----------------
__global__ void k_scanbsum(int nb, int n) {
    __shared__ int wtot[8];
    int t = threadIdx.x;               // 256 threads, nb <= 256
    int v = (t < nb) ? g_bsum[t] : 0;
    int lane = t & 31, w = t >> 5;
    int incl = v;
    #pragma unroll
    for (int off = 1; off < 32; off <<= 1) {
        int u = __shfl_up_sync(0xffffffffu, incl, off);
        if (lane >= off) incl += u;
    }
    if (lane == 31) wtot[w] = incl;
    __syncthreads();
    if (w == 0 && lane < 8) {
        int x = wtot[lane];
        int ix = x;
        #pragma unroll
        for (int off = 1; off < 8; off <<= 1) {
            int u = __shfl_up_sync(0xffu, ix, off);
            if (lane >= off) ix += u;
        }
        wtot[lane] = ix - x;           // exclusive warp offsets
    }
    __syncthreads();
    int excl = wtot[w] + (incl - v);
    if (t < nb) g_boff[t] = excl;
    if (t == 255) g_rowptr[n] = excl + v;
}

// ---------------- phase C: rowptr + dinv + cursor init ----------------
__global__ void k_rowptr(int n) {
    __shared__ int woff[8];
    int b = blockIdx.x, t = threadIdx.x;
    int i0 = b * SCAN_CHUNK + t * 2;
    int d0 = (i0     < n) ? g_deg[i0]     : 0;
    int d1 = (i0 + 1 < n) ? g_deg[i0 + 1] : 0;
    int s = d0 + d1;
    int lane = t & 31, w = t >> 5;
    int incl = s;
    #pragma unroll
    for (int off = 1; off < 32; off <<= 1) {
        int u = __shfl_up_sync(0xffffffffu, incl, off);
        if (lane >= off) incl += u;
    }
    if (lane == 31) woff[w] = incl;
    __syncthreads();
    if (w == 0 && lane < 8) {
        int x = woff[lane];
        int ix = x;
        #pragma unroll
        for (int off = 1; off < 8; off <<= 1) {
            int u = __shfl_up_sync(0xffu, ix, off);
            if (lane >= off) ix += u;
        }
        woff[lane] = ix - x;
    }
    __syncthreads();
    int base = g_boff[b] + woff[w] + (incl - s);
    if (i0 < n) {
        g_rowptr[i0] = base;
        g_cursor[i0] = base;
        g_dinv[i0]   = rsqrtf((float)(d0 + 1));
    }
    if (i0 + 1 < n) {
        g_rowptr[i0 + 1] = base + d0;
        g_cursor[i0 + 1] = base + d0;
        g_dinv[i0 + 1]   = rsqrtf((float)(d1 + 1));
    }
}

// ---------------- CSR fill (counting-sort placement) ----------------
__global__ void k_fill(const void* __restrict__ ei, int n, int e) {
    int i = blockIdx.x * blockDim.x + threadIdx.x;
    if (i >= e) return;
    int s, v;
    if (g_is64) {
        s = (int)((const long long*)ei)[i];
        v = (int)((const long long*)ei + e)[i];
    } else {
        s = ((const int*)ei)[i];
        v = ((const int*)ei + e)[i];
    }
    if ((unsigned)v < (unsigned)n && (unsigned)s < (unsigned)n) {
        int pos = atomicAdd(&g_cursor[v], 1);
        g_col[pos] = s;
    }
}

// ---------------- GEMM: g_h[i][j] = dinv[i] * dot(in[i,:], W[:,j]) ----------------
// BM=128, BN=64, BK=32; 128 threads; 8x8 register tile per thread.
// Xs stored k-major (transposed) so both operands stream as float4 LDS.
template<int K, bool FROM_GA>
__global__ void k_gemm(const float* __restrict__ in, const float* __restrict__ W, int n) {
    const int BM = 128, BN = 64, BK = 32;
    __shared__ float Xs[BK][BM + 4];   // stride 132 floats: 16B-aligned rows, 2-way store conflict only
    __shared__ float Ws[BK][BN];
    int tid = threadIdx.x;             // 128 threads
    int tx = tid & 7;                  // 0..7  -> cols tx*8..tx*8+7
    int ty = tid >> 3;                 // 0..15 -> rows ty*8..ty*8+7
    int row0 = blockIdx.x * BM;

    const float* src = FROM_GA ? (const float*)g_a : in;

    float acc[8][8] = {};

    for (int k0 = 0; k0 < K; k0 += BK) {
        // W chunk: BK x 64, contiguous. 512 float4s, 4 per thread.
        #pragma unroll
        for (int l = tid; l < BK * BN / 4; l += 128) {
            ((float4*)Ws)[0] = ((float4*)Ws)[0]; // no-op to keep compiler quiet about aliasing
            int r = l >> 4, c = l & 15;
            *(float4*)&Ws[r][c * 4] = *(const float4*)(W + (size_t)(k0 + r) * BN + c * 4);
        }
        // X chunk: BM rows x BK cols -> transposed into Xs. 1024 float4s, 8 per thread.
        #pragma unroll
        for (int l = tid; l < BM * BK / 4; l += 128) {
            int r  = l >> 3;           // row in tile (BK/4 = 8 float4 per row)
            int c4 = l & 7;
            int grow = row0 + r;
            float4 v = make_float4(0.f, 0.f, 0.f, 0.f);
            if (grow < n)
                v = *(const float4*)(src + (size_t)grow * K + k0 + c4 * 4);
            Xs[c4 * 4 + 0][r] = v.x;
            Xs[c4 * 4 + 1][r] = v.y;
            Xs[c4 * 4 + 2][r] = v.z;
            Xs[c4 * 4 + 3][r] = v.w;
        }
        __syncthreads();

        #pragma unroll
        for (int k = 0; k < BK; k++) {
            float4 a0 = *(float4*)&Xs[k][ty * 8];
            float4 a1 = *(float4*)&Xs[k][ty * 8 + 4];
            float4 b0 = *(float4*)&Ws[k][tx * 8];
            float4 b1 = *(float4*)&Ws[k][tx * 8 + 4];
            float a[8] = {a0.x, a0.y, a0.z, a0.w, a1.x, a1.y, a1.z, a1.w};
            float bb[8] = {b0.x, b0.y, b0.z, b0.w, b1.x, b1.y, b1.z, b1.w};
            #pragma unroll
            for (int r = 0; r < 8; r++)
                #pragma unroll
                for (int c = 0; c < 8; c++)
                    acc[r][c] = fmaf(a[r], bb[c], acc[r][c]);
        }
        __syncthreads();
    }

    #pragma unroll
    for (int r = 0; r < 8; r++) {
        int grow = row0 + ty * 8 + r;
        if (grow < n) {
            float dv = g_dinv[grow];
            float4 o0 = make_float4(acc[r][0] * dv, acc[r][1] * dv,
                                    acc[r][2] * dv, acc[r][3] * dv);
            float4 o1 = make_float4(acc[r][4] * dv, acc[r][5] * dv,
                                    acc[r][6] * dv, acc[r][7] * dv);
            *(float4*)(g_h + (size_t)grow * 64 + tx * 8)     = o0;
            *(float4*)(g_h + (size_t)grow * 64 + tx * 8 + 4) = o1;
        }
    }
}

// ---------------- aggregation: warp per node ----------------
template<bool TO_GA>
__global__ void k_agg(const float* __restrict__ bias, float* __restrict__ out, int n) {
    int warp = (blockIdx.x * blockDim.x + threadIdx.x) >> 5;
    int lane = threadIdx.x & 31;
    if (warp >= n) return;
    int v = warp;

    const float* h = (const float*)g_h;
    float2 acc = *(const float2*)(h + (size_t)v * 64 + lane * 2);
    int r0 = g_rowptr[v], r1 = g_rowptr[v + 1];
    int e = r0;
    for (; e + 1 < r1; e += 2) {
        int s0 = __ldg(&g_col[e]);
        int s1 = __ldg(&g_col[e + 1]);
        float2 m0 = *(const float2*)(h + (size_t)s0 * 64 + lane * 2);
        float2 m1 = *(const float2*)(h + (size_t)s1 * 64 + lane * 2);
        acc.x += m0.x + m1.x; acc.y += m0.y + m1.y;
    }
    if (e < r1) {
        int s0 = __ldg(&g_col[e]);
        float2 m0 = *(const float2*)(h + (size_t)s0 * 64 + lane * 2);
        acc.x += m0.x; acc.y += m0.y;
    }
    float dv = g_dinv[v];
    float2 bb = *(const float2*)(bias + lane * 2);
    float ox = fmaf(dv, acc.x, bb.x);
    float oy = fmaf(dv, acc.y, bb.y);
    if (TO_GA) {
        ox = fmaxf(ox, 0.f); oy = fmaxf(oy, 0.f);
        *(float2*)(g_a + (size_t)v * 64 + lane * 2) = make_float2(ox, oy);
    } else {
        *(float2*)(out + (size_t)v * 64 + lane * 2) = make_float2(ox, oy);
    }
}

// ---------------- launch ----------------
extern "C" void kernel_launch(void* const* d_in, const int* in_sizes, int n_in,
                              void* d_out, int out_size) {
    const float* x  = (const float*)d_in[0];
    const void*  ei = d_in[1];
    const float* W1 = (const float*)d_in[2];
    const float* b1 = (const float*)d_in[3];
    const float* W2 = (const float*)d_in[4];
    const float* b2 = (const float*)d_in[5];
    float* out = (float*)d_out;

    int n = in_sizes[0] / DIN;     // 100000
    int e = in_sizes[1] / 2;       // 1000000
    int nb = (n + SCAN_CHUNK - 1) / SCAN_CHUNK;   // 196

    k_detect  <<<1, 32>>>(ei, n, e);
    k_init    <<<(n + 255) / 256, 256>>>(n);
    k_count   <<<(e + 255) / 256, 256>>>(ei, n, e);
    k_part    <<<nb, 256>>>(n);
    k_scanbsum<<<1, 256>>>(nb, n);
    k_rowptr  <<<nb, 256>>>(n);
    k_fill    <<<(e + 255) / 256, 256>>>(ei, n, e);

    // layer 1: h = dinv * (x @ W1); a = relu(dinv*(h[v]+sum h[src]) + b1)
    k_gemm<DIN, false><<<(n + 127) / 128, 128>>>(x, W1, n);
    k_agg<true><<<(n * 32 + 255) / 256, 256>>>(b1, nullptr, n);

    // layer 2: h = dinv * (a @ W2); out = dinv*(h[v]+sum h[src]) + b2
    k_gemm<DH, true><<<(n + 127) / 128, 128>>>(nullptr, W2, n);
    k_agg<false><<<(n * 32 + 255) / 256, 256>>>(b2, out, n);
}

// round 6
// speedup vs baseline: 1.2206x; 1.2206x over previous
#include <cuda_runtime.h>
#include <cuda_fp16.h>
#include <cstdint>

#define MAXN 100000
#define MAXE 1000000
#define DIN 128
#define DH  64
#define SCAN_CHUNK 512
#define MAXB 256   // >= ceil(MAXN/SCAN_CHUNK) = 196

// ---- scratch (no allocations allowed; referenced only from device code) ----
__device__ int   g_deg[MAXN];
__device__ int   g_rowptr[MAXN + 1];
__device__ int   g_cursor[MAXN];
__device__ int   g_col[MAXE];
__device__ float g_dinv[MAXN];
__device__ int   g_bsum[MAXB];
__device__ int   g_boff[MAXB];
__device__ __align__(16) __half2 g_h16[(size_t)MAXN * 32]; // dinv-scaled GEMM output, fp16
__device__ __align__(16) float   g_a[(size_t)MAXN * 64];   // layer-1 activations, fp32
__device__ int   g_is64;                                    // edge dtype flag

// ---------------- dtype detection: int64 vs int32 edge_index ----------------
__global__ void k_detect(const void* ei, int n, int e) {
    const long long* p = (const long long*)ei;
    int lane = threadIdx.x;
    int bad = 0;
    #pragma unroll
    for (int j = 0; j < 2; j++) {
        int i = lane * 2 + j;
        if (i < e) {
            long long v = p[i];
            if (v < 0 || v >= n) bad = 1;
        }
    }
    unsigned m = __ballot_sync(0xffffffffu, bad);
    if (lane == 0) g_is64 = (m == 0u);
}

// ---------------- init: zero deg ----------------
__global__ void k_init(int n) {
    int i = blockIdx.x * blockDim.x + threadIdx.x;
    if (i < n) g_deg[i] = 0;
}

// ---------------- degree count over dst ----------------
__global__ void k_count(const void* __restrict__ ei, int n, int e) {
    int i = blockIdx.x * blockDim.x + threadIdx.x;
    if (i >= e) return;
    int v;
    if (g_is64) v = (int)((const long long*)ei + e)[i];
    else        v = ((const int*)ei + e)[i];
    if ((unsigned)v < (unsigned)n) atomicAdd(&g_deg[v], 1);
}

// ---------------- phase A: per-block sums of deg ----------------
__global__ void k_part(int n) {
    __shared__ int wsum[8];
    int b = blockIdx.x, t = threadIdx.x;
    int i0 = b * SCAN_CHUNK + t * 2;
    int d0 = (i0     < n) ? g_deg[i0]     : 0;
    int d1 = (i0 + 1 < n) ? g_deg[i0 + 1] : 0;
    int s = d0 + d1;
    #pragma unroll
    for (int off = 16; off > 0; off >>= 1)
        s += __shfl_down_sync(0xffffffffu, s, off);
    int lane = t & 31, w = t >> 5;
    if (lane == 0) wsum[w] = s;
    __syncthreads();
    if (t == 0) {
        int tot = 0;
        #pragma unroll
        for (int k = 0; k < 8; k++) tot += wsum[k];
        g_bsum[b] = tot;
    }
}

// ---------------- phase B: scan block sums (single block) ----------------
__global__ void k_scanbsum(int nb, int n) {
    __shared__ int wtot[8];
    int t = threadIdx.x;               // 256 threads, nb <= 256
    int v = (t < nb) ? g_bsum[t] : 0;
    int lane = t & 31, w = t >> 5;
    int incl = v;
    #pragma unroll
    for (int off = 1; off < 32; off <<= 1) {
        int u = __shfl_up_sync(0xffffffffu, incl, off);
        if (lane >= off) incl += u;
    }
    if (lane == 31) wtot[w] = incl;
    __syncthreads();
    if (w == 0 && lane < 8) {
        int x = wtot[lane];
        int ix = x;
        #pragma unroll
        for (int off = 1; off < 8; off <<= 1) {
            int u = __shfl_up_sync(0xffu, ix, off);
            if (lane >= off) ix += u;
        }
        wtot[lane] = ix - x;           // exclusive warp offsets
    }
    __syncthreads();
    int excl = wtot[w] + (incl - v);
    if (t < nb) g_boff[t] = excl;
    if (t == 255) g_rowptr[n] = excl + v;
}

// ---------------- phase C: rowptr + dinv + cursor init ----------------
__global__ void k_rowptr(int n) {
    __shared__ int woff[8];
    int b = blockIdx.x, t = threadIdx.x;
    int i0 = b * SCAN_CHUNK + t * 2;
    int d0 = (i0     < n) ? g_deg[i0]     : 0;
    int d1 = (i0 + 1 < n) ? g_deg[i0 + 1] : 0;
    int s = d0 + d1;
    int lane = t & 31, w = t >> 5;
    int incl = s;
    #pragma unroll
    for (int off = 1; off < 32; off <<= 1) {
        int u = __shfl_up_sync(0xffffffffu, incl, off);
        if (lane >= off) incl += u;
    }
    if (lane == 31) woff[w] = incl;
    __syncthreads();
    if (w == 0 && lane < 8) {
        int x = woff[lane];
        int ix = x;
        #pragma unroll
        for (int off = 1; off < 8; off <<= 1) {
            int u = __shfl_up_sync(0xffu, ix, off);
            if (lane >= off) ix += u;
        }
        woff[lane] = ix - x;
    }
    __syncthreads();
    int base = g_boff[b] + woff[w] + (incl - s);
    if (i0 < n) {
        g_rowptr[i0] = base;
        g_cursor[i0] = base;
        g_dinv[i0]   = rsqrtf((float)(d0 + 1));
    }
    if (i0 + 1 < n) {
        g_rowptr[i0 + 1] = base + d0;
        g_cursor[i0 + 1] = base + d0;
        g_dinv[i0 + 1]   = rsqrtf((float)(d1 + 1));
    }
}

// ---------------- CSR fill (counting-sort placement) ----------------
__global__ void k_fill(const void* __restrict__ ei, int n, int e) {
    int i = blockIdx.x * blockDim.x + threadIdx.x;
    if (i >= e) return;
    int s, v;
    if (g_is64) {
        s = (int)((const long long*)ei)[i];
        v = (int)((const long long*)ei + e)[i];
    } else {
        s = ((const int*)ei)[i];
        v = ((const int*)ei + e)[i];
    }
    if ((unsigned)v < (unsigned)n && (unsigned)s < (unsigned)n) {
        int pos = atomicAdd(&g_cursor[v], 1);
        g_col[pos] = s;
    }
}

// ---------------- GEMM: g_h16[i][j] = fp16( dinv[i] * dot(in[i,:], W[:,j]) ) ----
// Round-3 config (known good): 256 threads, 64x64 tile, 4x4 register tile.
template<int K, bool FROM_GA>
__global__ void k_gemm(const float* __restrict__ in, const float* __restrict__ W, int n) {
    const int BM = 64, BK = 64;
    __shared__ float Xs[BM][BK + 4];
    __shared__ float Ws[BK][64];
    int tid = threadIdx.x;
    int tx = tid & 15, ty = tid >> 4;
    int row0 = blockIdx.x * BM;

    const float* src = FROM_GA ? (const float*)g_a : in;

    float acc[4][4] = {};

    for (int k0 = 0; k0 < K; k0 += BK) {
        for (int l = tid; l < BK * 64 / 4; l += 256) {
            ((float4*)Ws)[l] = ((const float4*)(W + (size_t)k0 * 64))[l];
        }
        for (int l = tid; l < BM * BK / 4; l += 256) {
            int r = l >> 4;
            int c4 = l & 15;
            int grow = row0 + r;
            float4 v = make_float4(0.f, 0.f, 0.f, 0.f);
            if (grow < n)
                v = *(const float4*)(src + (size_t)grow * K + k0 + c4 * 4);
            *(float4*)&Xs[r][c4 * 4] = v;
        }
        __syncthreads();

        #pragma unroll
        for (int k = 0; k < BK; k++) {
            float a[4];
            #pragma unroll
            for (int r = 0; r < 4; r++) a[r] = Xs[ty * 4 + r][k];
            float4 bv = *(float4*)&Ws[k][tx * 4];
            #pragma unroll
            for (int r = 0; r < 4; r++) {
                acc[r][0] += a[r] * bv.x;
                acc[r][1] += a[r] * bv.y;
                acc[r][2] += a[r] * bv.z;
                acc[r][3] += a[r] * bv.w;
            }
        }
        __syncthreads();
    }

    #pragma unroll
    for (int r = 0; r < 4; r++) {
        int grow = row0 + ty * 4 + r;
        if (grow < n) {
            float dv = g_dinv[grow];
            __half2 p0 = __floats2half2_rn(acc[r][0] * dv, acc[r][1] * dv);
            __half2 p1 = __floats2half2_rn(acc[r][2] * dv, acc[r][3] * dv);
            // cols tx*4..tx*4+3 -> half2 slots grow*32 + tx*2, +1  (8B aligned)
            __half2* dst = g_h16 + (size_t)grow * 32 + tx * 2;
            dst[0] = p0;
            dst[1] = p1;
        }
    }
}

// ---------------- aggregation: warp per node ----------------
// out[v][:] = dinv[v] * (h[v][:] + sum_{s in row(v)} h[s][:]) + bias
// h rows are fp16 (half2 per lane = 128B per row read per edge).
template<bool TO_GA>
__global__ void k_agg(const float* __restrict__ bias, float* __restrict__ out, int n) {
    int warp = (blockIdx.x * blockDim.x + threadIdx.x) >> 5;
    int lane = threadIdx.x & 31;
    if (warp >= n) return;
    int v = warp;

    const __half2* h = (const __half2*)g_h16;
    float2 acc = __half22float2(h[(size_t)v * 32 + lane]);
    int r0 = g_rowptr[v], r1 = g_rowptr[v + 1];
    int e = r0;
    for (; e + 1 < r1; e += 2) {
        int s0 = __ldg(&g_col[e]);
        int s1 = __ldg(&g_col[e + 1]);
        float2 m0 = __half22float2(h[(size_t)s0 * 32 + lane]);
        float2 m1 = __half22float2(h[(size_t)s1 * 32 + lane]);
        acc.x += m0.x + m1.x; acc.y += m0.y + m1.y;
    }
    if (e < r1) {
        int s0 = __ldg(&g_col[e]);
        float2 m0 = __half22float2(h[(size_t)s0 * 32 + lane]);
        acc.x += m0.x; acc.y += m0.y;
    }
    float dv = g_dinv[v];
    float2 bb = *(const float2*)(bias + lane * 2);
    float ox = fmaf(dv, acc.x, bb.x);
    float oy = fmaf(dv, acc.y, bb.y);
    if (TO_GA) {
        ox = fmaxf(ox, 0.f); oy = fmaxf(oy, 0.f);
        *(float2*)(g_a + (size_t)v * 64 + lane * 2) = make_float2(ox, oy);
    } else {
        *(float2*)(out + (size_t)v * 64 + lane * 2) = make_float2(ox, oy);
    }
}

// ---------------- launch ----------------
extern "C" void kernel_launch(void* const* d_in, const int* in_sizes, int n_in,
                              void* d_out, int out_size) {
    const float* x  = (const float*)d_in[0];
    const void*  ei = d_in[1];
    const float* W1 = (const float*)d_in[2];
    const float* b1 = (const float*)d_in[3];
    const float* W2 = (const float*)d_in[4];
    const float* b2 = (const float*)d_in[5];
    float* out = (float*)d_out;

    int n = in_sizes[0] / DIN;     // 100000
    int e = in_sizes[1] / 2;       // 1000000
    int nb = (n + SCAN_CHUNK - 1) / SCAN_CHUNK;   // 196

    k_detect  <<<1, 32>>>(ei, n, e);
    k_init    <<<(n + 255) / 256, 256>>>(n);
    k_count   <<<(e + 255) / 256, 256>>>(ei, n, e);
    k_part    <<<nb, 256>>>(n);
    k_scanbsum<<<1, 256>>>(nb, n);
    k_rowptr  <<<nb, 256>>>(n);
    k_fill    <<<(e + 255) / 256, 256>>>(ei, n, e);

    // layer 1: h = dinv * (x @ W1); a = relu(dinv*(h[v]+sum h[src]) + b1)
    k_gemm<DIN, false><<<(n + 63) / 64, 256>>>(x, W1, n);
    k_agg<true><<<(n * 32 + 255) / 256, 256>>>(b1, nullptr, n);

    // layer 2: h = dinv * (a @ W2); out = dinv*(h[v]+sum h[src]) + b2
    k_gemm<DH, true><<<(n + 63) / 64, 256>>>(nullptr, W2, n);
    k_agg<false><<<(n * 32 + 255) / 256, 256>>>(b2, out, n);
}

// round 7
// speedup vs baseline: 1.5902x; 1.3028x over previous
#include <cuda_runtime.h>
#include <cuda_fp16.h>
#include <cstdint>

#define MAXN 100000
#define MAXE 1000000
#define DIN 128
#define DH  64
#define SCAN_CHUNK 512
#define MAXB 256   // >= ceil(MAXN/SCAN_CHUNK) = 196

// ---- scratch (no allocations allowed; referenced only from device code) ----
__device__ int   g_deg[MAXN];
__device__ int   g_rowptr[MAXN + 1];
__device__ int   g_cursor[MAXN];
__device__ int   g_col[MAXE];
__device__ float g_dinv[MAXN];
__device__ int   g_bsum[MAXB];
__device__ int   g_boff[MAXB];
__device__ __align__(16) __half2 g_h16[(size_t)MAXN * 32]; // dinv-scaled GEMM output, fp16
__device__ __align__(16) float   g_a[(size_t)MAXN * 64];   // layer-1 activations, fp32
__device__ int   g_is64;                                    // edge dtype flag

// ---------------- dtype detection: int64 vs int32 edge_index ----------------
__global__ void k_detect(const void* ei, int n, int e) {
    const long long* p = (const long long*)ei;
    int lane = threadIdx.x;
    int bad = 0;
    #pragma unroll
    for (int j = 0; j < 2; j++) {
        int i = lane * 2 + j;
        if (i < e) {
            long long v = p[i];
            if (v < 0 || v >= n) bad = 1;
        }
    }
    unsigned m = __ballot_sync(0xffffffffu, bad);
    if (lane == 0) g_is64 = (m == 0u);
}

// ---------------- init: zero deg ----------------
__global__ void k_init(int n) {
    int i = blockIdx.x * blockDim.x + threadIdx.x;
    if (i < n) g_deg[i] = 0;
}

// ---------------- degree count over dst ----------------
__global__ void k_count(const void* __restrict__ ei, int n, int e) {
    int i = blockIdx.x * blockDim.x + threadIdx.x;
    if (i >= e) return;
    int v;
    if (g_is64) v = (int)((const long long*)ei + e)[i];
    else        v = ((const int*)ei + e)[i];
    if ((unsigned)v < (unsigned)n) atomicAdd(&g_deg[v], 1);
}

// ---------------- phase A: per-block sums of deg ----------------
__global__ void k_part(int n) {
    __shared__ int wsum[8];
    int b = blockIdx.x, t = threadIdx.x;
    int i0 = b * SCAN_CHUNK + t * 2;
    int d0 = (i0     < n) ? g_deg[i0]     : 0;
    int d1 = (i0 + 1 < n) ? g_deg[i0 + 1] : 0;
    int s = d0 + d1;
    #pragma unroll
    for (int off = 16; off > 0; off >>= 1)
        s += __shfl_down_sync(0xffffffffu, s, off);
    int lane = t & 31, w = t >> 5;
    if (lane == 0) wsum[w] = s;
    __syncthreads();
    if (t == 0) {
        int tot = 0;
        #pragma unroll
        for (int k = 0; k < 8; k++) tot += wsum[k];
        g_bsum[b] = tot;
    }
}

// ---------------- phase B: scan block sums (single block) ----------------
__global__ void k_scanbsum(int nb, int n) {
    __shared__ int wtot[8];
    int t = threadIdx.x;               // 256 threads, nb <= 256
    int v = (t < nb) ? g_bsum[t] : 0;
    int lane = t & 31, w = t >> 5;
    int incl = v;
    #pragma unroll
    for (int off = 1; off < 32; off <<= 1) {
        int u = __shfl_up_sync(0xffffffffu, incl, off);
        if (lane >= off) incl += u;
    }
    if (lane == 31) wtot[w] = incl;
    __syncthreads();
    if (w == 0 && lane < 8) {
        int x = wtot[lane];
        int ix = x;
        #pragma unroll
        for (int off = 1; off < 8; off <<= 1) {
            int u = __shfl_up_sync(0xffu, ix, off);
            if (lane >= off) ix += u;
        }
        wtot[lane] = ix - x;           // exclusive warp offsets
    }
    __syncthreads();
    int excl = wtot[w] + (incl - v);
    if (t < nb) g_boff[t] = excl;
    if (t == 255) g_rowptr[n] = excl + v;
}

// ---------------- phase C: rowptr + dinv + cursor init ----------------
__global__ void k_rowptr(int n) {
    __shared__ int woff[8];
    int b = blockIdx.x, t = threadIdx.x;
    int i0 = b * SCAN_CHUNK + t * 2;
    int d0 = (i0     < n) ? g_deg[i0]     : 0;
    int d1 = (i0 + 1 < n) ? g_deg[i0 + 1] : 0;
    int s = d0 + d1;
    int lane = t & 31, w = t >> 5;
    int incl = s;
    #pragma unroll
    for (int off = 1; off < 32; off <<= 1) {
        int u = __shfl_up_sync(0xffffffffu, incl, off);
        if (lane >= off) incl += u;
    }
    if (lane == 31) woff[w] = incl;
    __syncthreads();
    if (w == 0 && lane < 8) {
        int x = woff[lane];
        int ix = x;
        #pragma unroll
        for (int off = 1; off < 8; off <<= 1) {
            int u = __shfl_up_sync(0xffu, ix, off);
            if (lane >= off) ix += u;
        }
        woff[lane] = ix - x;
    }
    __syncthreads();
    int base = g_boff[b] + woff[w] + (incl - s);
    if (i0 < n) {
        g_rowptr[i0] = base;
        g_cursor[i0] = base;
        g_dinv[i0]   = rsqrtf((float)(d0 + 1));
    }
    if (i0 + 1 < n) {
        g_rowptr[i0 + 1] = base + d0;
        g_cursor[i0 + 1] = base + d0;
        g_dinv[i0 + 1]   = rsqrtf((float)(d1 + 1));
    }
}

// ---------------- CSR fill (counting-sort placement) ----------------
__global__ void k_fill(const void* __restrict__ ei, int n, int e) {
    int i = blockIdx.x * blockDim.x + threadIdx.x;
    if (i >= e) return;
    int s, v;
    if (g_is64) {
        s = (int)((const long long*)ei)[i];
        v = (int)((const long long*)ei + e)[i];
    } else {
        s = ((const int*)ei)[i];
        v = ((const int*)ei + e)[i];
    }
    if ((unsigned)v < (unsigned)n && (unsigned)s < (unsigned)n) {
        int pos = atomicAdd(&g_cursor[v], 1);
        g_col[pos] = s;
    }
}

// ---------------- Tensor-core GEMM: g_h16[i][j] = fp16(dinv[i]*dot(in[i,:],W[:,j]))
// BM=128, BN=64, BK=64; 256 threads / 8 warps; warp tile 32x32 (2x4 m16n8k16).
// fp32 inputs converted to fp16 during smem staging; fp32 accumulate.
template<int K, bool FROM_GA>
__global__ void k_gemm_tc(const float* __restrict__ in, const float* __restrict__ W, int n) {
    const int LDA = 72;  // halfs per smem row (144B = 9*16B: ldmatrix-aligned, 4-bank rotation)
    const int LDB = 72;
    __shared__ __align__(16) __half Asm[128 * LDA];
    __shared__ __align__(16) __half Bsm[64 * LDB];

    int tid  = threadIdx.x;
    int warp = tid >> 5, lane = tid & 31;
    int wm = warp & 3, wn = warp >> 2;     // 4 warps in M, 2 in N
    int row0 = blockIdx.x * 128;
    const float* src = FROM_GA ? (const float*)g_a : in;

    float acc[2][4][4];
    #pragma unroll
    for (int i = 0; i < 2; i++)
        #pragma unroll
        for (int j = 0; j < 4; j++)
            #pragma unroll
            for (int q = 0; q < 4; q++) acc[i][j][q] = 0.f;

    for (int k0 = 0; k0 < K; k0 += 64) {
        // stage A: 128 rows x 64 halfs (fp32 -> fp16)
        #pragma unroll
        for (int l = tid; l < 128 * 16; l += 256) {
            int r = l >> 4, c4 = l & 15;
            int grow = row0 + r;
            float4 v = make_float4(0.f, 0.f, 0.f, 0.f);
            if (grow < n)
                v = *(const float4*)(src + (size_t)grow * K + k0 + c4 * 4);
            __half* p = Asm + r * LDA + c4 * 4;
            *(__half2*)(p)     = __floats2half2_rn(v.x, v.y);
            *(__half2*)(p + 2) = __floats2half2_rn(v.z, v.w);
        }
        // stage B: 64 rows (k) x 64 halfs (n)
        #pragma unroll
        for (int l = tid; l < 64 * 16; l += 256) {
            int r = l >> 4, c4 = l & 15;
            float4 v = *(const float4*)(W + (size_t)(k0 + r) * 64 + c4 * 4);
            __half* p = Bsm + r * LDB + c4 * 4;
            *(__half2*)(p)     = __floats2half2_rn(v.x, v.y);
            *(__half2*)(p + 2) = __floats2half2_rn(v.z, v.w);
        }
        __syncthreads();

        #pragma unroll
        for (int kk = 0; kk < 4; kk++) {   // four k16 steps
            // A fragments: 2 m-atoms, ldmatrix.x4 each
            uint32_t a[2][4];
            #pragma unroll
            for (int ma = 0; ma < 2; ma++) {
                int r = wm * 32 + ma * 16 + (lane & 7) + ((lane >> 3) & 1) * 8;
                int c = kk * 16 + (lane >> 4) * 8;
                uint32_t addr = (uint32_t)__cvta_generic_to_shared(Asm + r * LDA + c);
                asm volatile("ldmatrix.sync.aligned.m8n8.x4.shared.b16 {%0,%1,%2,%3}, [%4];"
                             : "=r"(a[ma][0]), "=r"(a[ma][1]), "=r"(a[ma][2]), "=r"(a[ma][3])
                             : "r"(addr));
            }
            // B fragments: 4 n-atoms via 2x ldmatrix.x4.trans
            uint32_t b[4][2];
            #pragma unroll
            for (int p = 0; p < 2; p++) {
                int krow = kk * 16 + (lane & 7) + ((lane >> 3) & 1) * 8;
                int ncol = wn * 32 + (p * 2 + (lane >> 4)) * 8;
                uint32_t addr = (uint32_t)__cvta_generic_to_shared(Bsm + krow * LDB + ncol);
                asm volatile("ldmatrix.sync.aligned.m8n8.x4.trans.shared.b16 {%0,%1,%2,%3}, [%4];"
                             : "=r"(b[p*2][0]), "=r"(b[p*2][1]), "=r"(b[p*2+1][0]), "=r"(b[p*2+1][1])
                             : "r"(addr));
            }
            #pragma unroll
            for (int ma = 0; ma < 2; ma++)
                #pragma unroll
                for (int nb = 0; nb < 4; nb++) {
                    asm volatile(
                        "mma.sync.aligned.m16n8k16.row.col.f32.f16.f16.f32 "
                        "{%0,%1,%2,%3}, {%4,%5,%6,%7}, {%8,%9}, {%0,%1,%2,%3};"
                        : "+f"(acc[ma][nb][0]), "+f"(acc[ma][nb][1]),
                          "+f"(acc[ma][nb][2]), "+f"(acc[ma][nb][3])
                        : "r"(a[ma][0]), "r"(a[ma][1]), "r"(a[ma][2]), "r"(a[ma][3]),
                          "r"(b[nb][0]), "r"(b[nb][1]));
                }
        }
        __syncthreads();
    }

    // epilogue: scale by dinv[row], pack fp16, store
    int groupID = lane >> 2, tid4 = lane & 3;
    #pragma unroll
    for (int ma = 0; ma < 2; ma++) {
        int r0 = row0 + wm * 32 + ma * 16 + groupID;
        int r1 = r0 + 8;
        float dv0 = (r0 < n) ? g_dinv[r0] : 0.f;
        float dv1 = (r1 < n) ? g_dinv[r1] : 0.f;
        #pragma unroll
        for (int nb = 0; nb < 4; nb++) {
            int col2 = wn * 16 + nb * 4 + tid4;   // half2 slot within row of 32
            if (r0 < n)
                g_h16[(size_t)r0 * 32 + col2] =
                    __floats2half2_rn(acc[ma][nb][0] * dv0, acc[ma][nb][1] * dv0);
            if (r1 < n)
                g_h16[(size_t)r1 * 32 + col2] =
                    __floats2half2_rn(acc[ma][nb][2] * dv1, acc[ma][nb][3] * dv1);
        }
    }
}

// ---------------- aggregation: warp per node ----------------
// out[v][:] = dinv[v] * (h[v][:] + sum_{s in row(v)} h[s][:]) + bias
template<bool TO_GA>
__global__ void k_agg(const float* __restrict__ bias, float* __restrict__ out, int n) {
    int warp = (blockIdx.x * blockDim.x + threadIdx.x) >> 5;
    int lane = threadIdx.x & 31;
    if (warp >= n) return;
    int v = warp;

    const __half2* h = (const __half2*)g_h16;
    float2 acc = __half22float2(h[(size_t)v * 32 + lane]);
    int r0 = g_rowptr[v], r1 = g_rowptr[v + 1];
    int e = r0;
    for (; e + 1 < r1; e += 2) {
        int s0 = __ldg(&g_col[e]);
        int s1 = __ldg(&g_col[e + 1]);
        float2 m0 = __half22float2(h[(size_t)s0 * 32 + lane]);
        float2 m1 = __half22float2(h[(size_t)s1 * 32 + lane]);
        acc.x += m0.x + m1.x; acc.y += m0.y + m1.y;
    }
    if (e < r1) {
        int s0 = __ldg(&g_col[e]);
        float2 m0 = __half22float2(h[(size_t)s0 * 32 + lane]);
        acc.x += m0.x; acc.y += m0.y;
    }
    float dv = g_dinv[v];
    float2 bb = *(const float2*)(bias + lane * 2);
    float ox = fmaf(dv, acc.x, bb.x);
    float oy = fmaf(dv, acc.y, bb.y);
    if (TO_GA) {
        ox = fmaxf(ox, 0.f); oy = fmaxf(oy, 0.f);
        *(float2*)(g_a + (size_t)v * 64 + lane * 2) = make_float2(ox, oy);
    } else {
        *(float2*)(out + (size_t)v * 64 + lane * 2) = make_float2(ox, oy);
    }
}

// ---------------- launch ----------------
extern "C" void kernel_launch(void* const* d_in, const int* in_sizes, int n_in,
                              void* d_out, int out_size) {
    const float* x  = (const float*)d_in[0];
    const void*  ei = d_in[1];
    const float* W1 = (const float*)d_in[2];
    const float* b1 = (const float*)d_in[3];
    const float* W2 = (const float*)d_in[4];
    const float* b2 = (const float*)d_in[5];
    float* out = (float*)d_out;

    int n = in_sizes[0] / DIN;     // 100000
    int e = in_sizes[1] / 2;       // 1000000
    int nb = (n + SCAN_CHUNK - 1) / SCAN_CHUNK;   // 196

    k_detect  <<<1, 32>>>(ei, n, e);
    k_init    <<<(n + 255) / 256, 256>>>(n);
    k_count   <<<(e + 255) / 256, 256>>>(ei, n, e);
    k_part    <<<nb, 256>>>(n);
    k_scanbsum<<<1, 256>>>(nb, n);
    k_rowptr  <<<nb, 256>>>(n);
    k_fill    <<<(e + 255) / 256, 256>>>(ei, n, e);

    // layer 1: h = dinv * (x @ W1); a = relu(dinv*(h[v]+sum h[src]) + b1)
    k_gemm_tc<DIN, false><<<(n + 127) / 128, 256>>>(x, W1, n);
    k_agg<true><<<(n * 32 + 255) / 256, 256>>>(b1, nullptr, n);

    // layer 2: h = dinv * (a @ W2); out = dinv*(h[v]+sum h[src]) + b2
    k_gemm_tc<DH, true><<<(n + 127) / 128, 256>>>(nullptr, W2, n);
    k_agg<false><<<(n * 32 + 255) / 256, 256>>>(b2, out, n);
}